// round 11
// baseline (speedup 1.0000x reference)
#include <cuda_runtime.h>
#include <cuda_fp16.h>
#include <cstdint>

// Problem constants (fixed by the dataset)
#define NU 100000
#define NI 50000
#define NT (NU + NI)        // 150000 total nodes
#define D  64               // factors
#define D4 (D / 4)          // 16 float4 per row
#define D8 (D / 8)          // 8 x uint4(fp16) per row
#define NLAYERS 3
#define NNZ_MAX 4800000

#define SCAN_THREADS 1024
#define SCAN_ITEMS   4
#define SCAN_CHUNK   (SCAN_THREADS * SCAN_ITEMS)          // 4096
#define SCAN_NB      ((NT + SCAN_CHUNK - 1) / SCAN_CHUNK) // 37

// Static device scratch (allocation is forbidden)
__device__ __half g_hA[(size_t)NT * D];    // ping-pong fp16 propagation buffers
__device__ __half g_hB[(size_t)NT * D];
__device__ int2   g_csr[NNZ_MAX];          // {col, val_bits} in CSR order
__device__ int    g_cnt[NT];               // per-row degree counts
__device__ int    g_rowptr[NT + 1];        // CSR row pointers
__device__ int    g_fill[NT];              // scatter fill cursors
__device__ int    g_bsum[SCAN_NB];         // scan block sums

__device__ __forceinline__ float2 h2f(unsigned u) {
    __half2 h = *reinterpret_cast<__half2*>(&u);
    return __half22float2(h);
}
__device__ __forceinline__ unsigned f2h(float a, float b) {
    __half2 h = __floats2half2_rn(a, b);
    return *reinterpret_cast<unsigned*>(&h);
}

// ---------------------------------------------------------------------------
// init: g_hA = fp16(concat(user_emb, item_emb)); acc (=d_out) = f32 concat;
//       zero g_cnt / g_fill. One thread per float4 (2.4M).
// ---------------------------------------------------------------------------
__global__ void lgcn_init(const float* __restrict__ ue,
                          const float* __restrict__ ie,
                          float* __restrict__ acc) {
    int i = blockIdx.x * blockDim.x + threadIdx.x;
    const int total4 = NT * D4;
    const int user4  = NU * D4;
    if (i < total4) {
        float4 v;
        if (i < user4) v = reinterpret_cast<const float4*>(ue)[i];
        else           v = reinterpret_cast<const float4*>(ie)[i - user4];
        reinterpret_cast<float4*>(acc)[i] = v;
        uint2 h;
        h.x = f2h(v.x, v.y);
        h.y = f2h(v.z, v.w);
        reinterpret_cast<uint2*>(g_hA)[i] = h;
    }
    if (i < NT) { g_cnt[i] = 0; g_fill[i] = 0; }
}

// ---------------------------------------------------------------------------
// histogram: count in-edges per destination row
// ---------------------------------------------------------------------------
__global__ void lgcn_hist(const int* __restrict__ row, int nnz) {
    int e = blockIdx.x * blockDim.x + threadIdx.x;
    if (e < nnz) atomicAdd(&g_cnt[row[e]], 1);
}

// ---------------------------------------------------------------------------
// exclusive scan of g_cnt[NT] -> g_rowptr (3 small kernels)
// ---------------------------------------------------------------------------
__global__ void lgcn_scan1() {
    __shared__ int sh[SCAN_THREADS];
    int t = threadIdx.x;
    int base = blockIdx.x * SCAN_CHUNK + t * SCAN_ITEMS;
    int v[SCAN_ITEMS];
    int s = 0;
#pragma unroll
    for (int j = 0; j < SCAN_ITEMS; j++) {
        int idx = base + j;
        v[j] = (idx < NT) ? g_cnt[idx] : 0;
        s += v[j];
    }
    sh[t] = s;
    __syncthreads();
    for (int off = 1; off < SCAN_THREADS; off <<= 1) {
        int x = sh[t];
        int y = (t >= off) ? sh[t - off] : 0;
        __syncthreads();
        sh[t] = x + y;
        __syncthreads();
    }
    int excl = sh[t] - s;
#pragma unroll
    for (int j = 0; j < SCAN_ITEMS; j++) {
        int idx = base + j;
        if (idx < NT) g_rowptr[idx] = excl;
        excl += v[j];
    }
    if (t == SCAN_THREADS - 1) g_bsum[blockIdx.x] = sh[SCAN_THREADS - 1];
}

__global__ void lgcn_scan2() {   // parallel 64-wide scan over SCAN_NB block sums
    __shared__ int sh[64];
    int t = threadIdx.x;
    int v = (t < SCAN_NB) ? g_bsum[t] : 0;
    sh[t] = v;
    __syncthreads();
    for (int off = 1; off < 64; off <<= 1) {
        int x = sh[t];
        int y = (t >= off) ? sh[t - off] : 0;
        __syncthreads();
        sh[t] = x + y;
        __syncthreads();
    }
    if (t < SCAN_NB) g_bsum[t] = sh[t] - v;   // exclusive
}

__global__ void lgcn_scan3(int nnz) {
    int i = blockIdx.x * blockDim.x + threadIdx.x;
    if (i < NT) g_rowptr[i] += g_bsum[i / SCAN_CHUNK];
    if (i == 0) g_rowptr[NT] = nnz;
}

// ---------------------------------------------------------------------------
// scatter edges into CSR order: g_csr[rowptr[r] + fill[r]++] = {col, val}
// ---------------------------------------------------------------------------
__global__ void lgcn_scatter(const int* __restrict__ row,
                             const int* __restrict__ col,
                             const float* __restrict__ val,
                             int nnz) {
    int e = blockIdx.x * blockDim.x + threadIdx.x;
    if (e >= nnz) return;
    int r = row[e];
    int pos = g_rowptr[r] + atomicAdd(&g_fill[r], 1);
    g_csr[pos] = make_int2(col[e], __float_as_int(val[e]));
}

// ---------------------------------------------------------------------------
// CSR SpMM (fp16 gather, f32 accumulate) fused with running-mean update.
//   next[r] = fp16( sum_{edges of r} val * cur[col] )
//   acc[r] += sum_f32   (last layer: acc = (acc + sum) * 0.25)
// 8 lanes per row; each lane owns 8 dims (16B of the 128B fp16 row).
// Edge (col,val) pairs loaded 8-wide, broadcast via shfl (width 8).
// cur/next resolved from __device__ symbols IN DEVICE CODE (host-side device
// symbols are host shadow addresses; ATS makes that silently wrong on GB300).
// ---------------------------------------------------------------------------
__global__ void lgcn_spmm_csr(float* __restrict__ acc, int flip, int last) {
    const __half* __restrict__ cur  = flip ? g_hB : g_hA;
    __half*       __restrict__ next = flip ? g_hA : g_hB;

    const unsigned FULL = 0xffffffffu;
    int t   = blockIdx.x * blockDim.x + threadIdx.x;
    int r   = t >> 3;          // row
    int seg = t & 7;           // 16B segment within the fp16 row
    if (r >= NT) return;

    int start = g_rowptr[r];
    int end   = g_rowptr[r + 1];

    float s0 = 0.f, s1 = 0.f, s2 = 0.f, s3 = 0.f;
    float s4 = 0.f, s5 = 0.f, s6 = 0.f, s7 = 0.f;
    const uint4* cur4 = reinterpret_cast<const uint4*>(cur);

    int k = start;
    for (; k + 8 <= end; k += 8) {       // full 8-edge chunks
        int2 cv = __ldg(&g_csr[k + seg]);
#pragma unroll
        for (int j = 0; j < 8; j++) {
            int   c = __shfl_sync(FULL, cv.x, j, 8);
            float v = __int_as_float(__shfl_sync(FULL, cv.y, j, 8));
            uint4 h = __ldg(cur4 + (size_t)c * D8 + seg);
            float2 f0 = h2f(h.x), f1 = h2f(h.y), f2 = h2f(h.z), f3 = h2f(h.w);
            s0 += v * f0.x; s1 += v * f0.y; s2 += v * f1.x; s3 += v * f1.y;
            s4 += v * f2.x; s5 += v * f2.y; s6 += v * f3.x; s7 += v * f3.y;
        }
    }
    if (k < end) {                        // tail (1..7 edges)
        int lim = end - k;
        int idx = k + seg;
        int2 cv = (idx < end) ? __ldg(&g_csr[idx]) : make_int2(0, 0);
        for (int j = 0; j < lim; j++) {
            int   c = __shfl_sync(FULL, cv.x, j, 8);
            float v = __int_as_float(__shfl_sync(FULL, cv.y, j, 8));
            uint4 h = __ldg(cur4 + (size_t)c * D8 + seg);
            float2 f0 = h2f(h.x), f1 = h2f(h.y), f2 = h2f(h.z), f3 = h2f(h.w);
            s0 += v * f0.x; s1 += v * f0.y; s2 += v * f1.x; s3 += v * f1.y;
            s4 += v * f2.x; s5 += v * f2.y; s6 += v * f3.x; s7 += v * f3.y;
        }
    }

    // store next layer input (fp16)
    uint4 o;
    o.x = f2h(s0, s1); o.y = f2h(s2, s3); o.z = f2h(s4, s5); o.w = f2h(s6, s7);
    reinterpret_cast<uint4*>(next)[(size_t)r * D8 + seg] = o;

    // running-mean update in f32 (lane covers 8 contiguous floats = 2 float4)
    float4* a4 = reinterpret_cast<float4*>(acc + (size_t)r * D + seg * 8);
    float4 a0 = a4[0], a1 = a4[1];
    a0.x += s0; a0.y += s1; a0.z += s2; a0.w += s3;
    a1.x += s4; a1.y += s5; a1.z += s6; a1.w += s7;
    if (last) {
        a0.x *= 0.25f; a0.y *= 0.25f; a0.z *= 0.25f; a0.w *= 0.25f;
        a1.x *= 0.25f; a1.y *= 0.25f; a1.z *= 0.25f; a1.w *= 0.25f;
    }
    a4[0] = a0; a4[1] = a1;
}

// ---------------------------------------------------------------------------
// launch
// Inputs (metadata order): user_emb f32 [NU*D], item_emb f32 [NI*D],
//                          adj_row i32 [NNZ], adj_col i32 [NNZ], adj_val f32 [NNZ]
// Output: mean_emb f32 [NT*D] (users then items)
// ---------------------------------------------------------------------------
extern "C" void kernel_launch(void* const* d_in, const int* in_sizes, int n_in,
                              void* d_out, int out_size) {
    const float* ue   = (const float*)d_in[0];
    const float* ie   = (const float*)d_in[1];
    const int*   arow = (const int*)d_in[2];
    const int*   acol = (const int*)d_in[3];
    const float* aval = (const float*)d_in[4];
    float* acc = (float*)d_out;

    int nnz = in_sizes[2];
    if (nnz > NNZ_MAX) nnz = NNZ_MAX;   // static scratch bound (dataset-fixed)

    const int THREADS = 256;
    const int total4   = NT * D4;                           // 2.4M
    const int gridInit = (total4 + THREADS - 1) / THREADS;  // also covers NT
    const int gridEdge = (nnz + THREADS - 1) / THREADS;
    const int gridRowP = (NT + THREADS - 1) / THREADS;
    const int gridSpmm = (NT * 8 + THREADS - 1) / THREADS;

    // build initial embeddings + CSR (once per launch/replay)
    lgcn_init<<<gridInit, THREADS>>>(ue, ie, acc);
    lgcn_hist<<<gridEdge, THREADS>>>(arow, nnz);
    lgcn_scan1<<<SCAN_NB, SCAN_THREADS>>>();
    lgcn_scan2<<<1, 64>>>();
    lgcn_scan3<<<gridRowP, THREADS>>>(nnz);
    lgcn_scatter<<<gridEdge, THREADS>>>(arow, acol, aval, nnz);

    // 3 propagation layers; cur/next resolved inside the kernel via flip
    for (int l = 0; l < NLAYERS; l++) {
        int last = (l == NLAYERS - 1) ? 1 : 0;
        lgcn_spmm_csr<<<gridSpmm, THREADS>>>(acc, l & 1, last);
    }
}

// round 12
// speedup vs baseline: 1.5525x; 1.5525x over previous
#include <cuda_runtime.h>
#include <cstdint>

// Problem constants (fixed by the dataset)
#define NU 100000
#define NI 50000
#define NT (NU + NI)        // 150000 total nodes
#define D  64               // factors
#define D4 (D / 4)          // 16 float4 per row
#define NLAYERS 3
#define NNZ_MAX 4800000

#define SCAN_THREADS 1024
#define SCAN_ITEMS   4
#define SCAN_CHUNK   (SCAN_THREADS * SCAN_ITEMS)          // 4096
#define SCAN_SHIFT   12                                   // log2(SCAN_CHUNK)
#define SCAN_NB      ((NT + SCAN_CHUNK - 1) / SCAN_CHUNK) // 37

// Static device scratch (allocation is forbidden)
__device__ float g_bufA[(size_t)NT * D];   // ping-pong embedding buffers (f32)
__device__ float g_bufB[(size_t)NT * D];
__device__ int2  g_csr[NNZ_MAX];           // {col, val_bits} in CSR order
__device__ int   g_cnt[NT];                // per-row degree counts
__device__ int   g_rowptr[NT];             // block-local exclusive prefix
__device__ int   g_fill[NT];               // scatter fill cursors
__device__ int   g_bsum[SCAN_NB];          // exclusive-scanned block sums

// ---------------------------------------------------------------------------
// init: bufA = concat(user_emb, item_emb); acc (=d_out) = bufA;
//       zero g_cnt / g_fill.
// ---------------------------------------------------------------------------
__global__ void lgcn_init(const float* __restrict__ ue,
                          const float* __restrict__ ie,
                          float* __restrict__ acc) {
    int i = blockIdx.x * blockDim.x + threadIdx.x;
    const int total4 = NT * D4;
    const int user4  = NU * D4;
    if (i < total4) {
        float4 v;
        if (i < user4) v = reinterpret_cast<const float4*>(ue)[i];
        else           v = reinterpret_cast<const float4*>(ie)[i - user4];
        reinterpret_cast<float4*>(g_bufA)[i] = v;
        reinterpret_cast<float4*>(acc)[i]    = v;
    }
    if (i < NT) { g_cnt[i] = 0; g_fill[i] = 0; }
}

// ---------------------------------------------------------------------------
// histogram: count in-edges per destination row
// ---------------------------------------------------------------------------
__global__ void lgcn_hist(const int* __restrict__ row, int nnz) {
    int e = blockIdx.x * blockDim.x + threadIdx.x;
    if (e < nnz) atomicAdd(&g_cnt[row[e]], 1);
}

// ---------------------------------------------------------------------------
// scan1: per-chunk (4096 rows) exclusive prefix into g_rowptr, totals to g_bsum
// scan2: exclusive scan of the 37 chunk totals (single small block)
// Final rowptr[r] = g_rowptr[r] + g_bsum[r >> SCAN_SHIFT]  (computed inline
// by scatter & spmm — no scan3 pass, one fewer launch)
// ---------------------------------------------------------------------------
__global__ void lgcn_scan1() {
    __shared__ int sh[SCAN_THREADS];
    int t = threadIdx.x;
    int base = blockIdx.x * SCAN_CHUNK + t * SCAN_ITEMS;
    int v[SCAN_ITEMS];
    int s = 0;
#pragma unroll
    for (int j = 0; j < SCAN_ITEMS; j++) {
        int idx = base + j;
        v[j] = (idx < NT) ? g_cnt[idx] : 0;
        s += v[j];
    }
    sh[t] = s;
    __syncthreads();
    for (int off = 1; off < SCAN_THREADS; off <<= 1) {
        int x = sh[t];
        int y = (t >= off) ? sh[t - off] : 0;
        __syncthreads();
        sh[t] = x + y;
        __syncthreads();
    }
    int excl = sh[t] - s;
#pragma unroll
    for (int j = 0; j < SCAN_ITEMS; j++) {
        int idx = base + j;
        if (idx < NT) g_rowptr[idx] = excl;
        excl += v[j];
    }
    if (t == SCAN_THREADS - 1) g_bsum[blockIdx.x] = sh[SCAN_THREADS - 1];
}

__global__ void lgcn_scan2() {
    __shared__ int sh[64];
    int t = threadIdx.x;
    int v = (t < SCAN_NB) ? g_bsum[t] : 0;
    sh[t] = v;
    __syncthreads();
    for (int off = 1; off < 64; off <<= 1) {
        int x = sh[t];
        int y = (t >= off) ? sh[t - off] : 0;
        __syncthreads();
        sh[t] = x + y;
        __syncthreads();
    }
    if (t < SCAN_NB) g_bsum[t] = sh[t] - v;   // exclusive
}

// ---------------------------------------------------------------------------
// scatter edges into CSR order (rowptr resolved inline with bsum)
// ---------------------------------------------------------------------------
__global__ void lgcn_scatter(const int* __restrict__ row,
                             const int* __restrict__ col,
                             const float* __restrict__ val,
                             int nnz) {
    int e = blockIdx.x * blockDim.x + threadIdx.x;
    if (e >= nnz) return;
    int r = row[e];
    int base = g_rowptr[r] + g_bsum[r >> SCAN_SHIFT];
    int pos  = base + atomicAdd(&g_fill[r], 1);
    g_csr[pos] = make_int2(col[e], __float_as_int(val[e]));
}

// ---------------------------------------------------------------------------
// CSR SpMM fused with running-mean update.
//   next[r] = sum_{edges of r} val * cur[col]   (plain store, no atomics)
//   acc[r] += sum      (last layer: acc = (acc + sum) * 0.25)
// 16 lanes per row, one float4 per lane. Edge (col,val) pairs loaded 16-wide,
// broadcast via shfl using the GROUP member mask (two 16-lane groups per warp
// can have different tail lengths — full-warp mask there is UB).
// Next chunk's int2 is prefetched before the inner gather loop to hide one
// L2 round-trip per chunk.
// cur/next resolved from __device__ symbols IN DEVICE CODE (host-side symbol
// addresses are host shadows; ATS makes that silently wrong on GB300).
// ---------------------------------------------------------------------------
__global__ void lgcn_spmm_csr(float* __restrict__ acc, int flip, int last, int nnz) {
    const float* __restrict__ cur  = flip ? g_bufB : g_bufA;
    float*       __restrict__ next = flip ? g_bufA : g_bufB;

    int t   = blockIdx.x * blockDim.x + threadIdx.x;
    int r   = t >> 4;          // row
    int seg = t & 15;          // float4 segment within row
    if (r >= NT) return;
    unsigned gmask = 0xFFFFu << (threadIdx.x & 16);   // this lane's 16-lane group

    int start = g_rowptr[r] + g_bsum[r >> SCAN_SHIFT];
    int end   = (r + 1 < NT) ? (g_rowptr[r + 1] + g_bsum[(r + 1) >> SCAN_SHIFT])
                             : nnz;

    float4 s = make_float4(0.f, 0.f, 0.f, 0.f);
    const float4* cur4 = reinterpret_cast<const float4*>(cur);

    int k = start;
    int2 cv = make_int2(0, 0);
    if (k + seg < end) cv = __ldg(&g_csr[k + seg]);

    // full 16-edge chunks, with prefetch of the following chunk's pairs
    for (; k + 16 <= end; ) {
        int2 use = cv;
        int kn = k + 16;
        if (kn + seg < end) cv = __ldg(&g_csr[kn + seg]);   // prefetch
#pragma unroll
        for (int j = 0; j < 16; j++) {
            int   c = __shfl_sync(gmask, use.x, j, 16);
            float v = __int_as_float(__shfl_sync(gmask, use.y, j, 16));
            float4 x = __ldg(cur4 + (size_t)c * D4 + seg);
            s.x += v * x.x; s.y += v * x.y; s.z += v * x.z; s.w += v * x.w;
        }
        k = kn;
    }
    // tail (0..15 edges) — trip count uniform within the 16-lane group
    int rem = end - k;
    for (int j = 0; j < rem; j++) {
        int   c = __shfl_sync(gmask, cv.x, j, 16);
        float v = __int_as_float(__shfl_sync(gmask, cv.y, j, 16));
        float4 x = __ldg(cur4 + (size_t)c * D4 + seg);
        s.x += v * x.x; s.y += v * x.y; s.z += v * x.z; s.w += v * x.w;
    }

    size_t o = (size_t)r * D4 + seg;
    reinterpret_cast<float4*>(next)[o] = s;

    float4 a = reinterpret_cast<float4*>(acc)[o];
    a.x += s.x; a.y += s.y; a.z += s.z; a.w += s.w;
    if (last) { a.x *= 0.25f; a.y *= 0.25f; a.z *= 0.25f; a.w *= 0.25f; }
    reinterpret_cast<float4*>(acc)[o] = a;
}

// ---------------------------------------------------------------------------
// launch
// Inputs (metadata order): user_emb f32 [NU*D], item_emb f32 [NI*D],
//                          adj_row i32 [NNZ], adj_col i32 [NNZ], adj_val f32 [NNZ]
// Output: mean_emb f32 [NT*D] (users then items)
// Launch order: init(0) hist(1) scan1(2) scan2(3) scatter(4) spmm(5,6,7)
// -> ncu capture slot (skip 5) lands on an spmm launch.
// ---------------------------------------------------------------------------
extern "C" void kernel_launch(void* const* d_in, const int* in_sizes, int n_in,
                              void* d_out, int out_size) {
    const float* ue   = (const float*)d_in[0];
    const float* ie   = (const float*)d_in[1];
    const int*   arow = (const int*)d_in[2];
    const int*   acol = (const int*)d_in[3];
    const float* aval = (const float*)d_in[4];
    float* acc = (float*)d_out;

    int nnz = in_sizes[2];
    if (nnz > NNZ_MAX) nnz = NNZ_MAX;   // static scratch bound (dataset-fixed)

    const int THREADS = 256;
    const int total4   = NT * D4;                           // 2.4M
    const int gridInit = (total4 + THREADS - 1) / THREADS;  // also covers NT
    const int gridEdge = (nnz + THREADS - 1) / THREADS;
    const int gridSpmm = (NT * 16 + THREADS - 1) / THREADS;

    lgcn_init<<<gridInit, THREADS>>>(ue, ie, acc);
    lgcn_hist<<<gridEdge, THREADS>>>(arow, nnz);
    lgcn_scan1<<<SCAN_NB, SCAN_THREADS>>>();
    lgcn_scan2<<<1, 64>>>();
    lgcn_scatter<<<gridEdge, THREADS>>>(arow, acol, aval, nnz);

    for (int l = 0; l < NLAYERS; l++) {
        int last = (l == NLAYERS - 1) ? 1 : 0;
        lgcn_spmm_csr<<<gridSpmm, THREADS>>>(acc, l & 1, last, nnz);
    }
}

// round 13
// speedup vs baseline: 2.0499x; 1.3204x over previous
#include <cuda_runtime.h>
#include <cuda_fp16.h>
#include <cstdint>

// Problem constants (fixed by the dataset)
#define NU 100000
#define NI 50000
#define NT (NU + NI)        // 150000 total nodes
#define D  64               // factors
#define D4 (D / 4)          // 16 float4 per f32 row
#define NLAYERS 3
#define NNZ_MAX 4800000

#define SCAN_THREADS 1024
#define SCAN_ITEMS   4
#define SCAN_CHUNK   (SCAN_THREADS * SCAN_ITEMS)          // 4096
#define SCAN_SHIFT   12                                   // log2(SCAN_CHUNK)
#define SCAN_NB      ((NT + SCAN_CHUNK - 1) / SCAN_CHUNK) // 37

// Static device scratch (allocation is forbidden)
__device__ __half g_h0[(size_t)NT * D];    // e0 (fp16)
__device__ __half g_h1[(size_t)NT * D];    // e1 (fp16)
__device__ __half g_h2[(size_t)NT * D];    // e2 (fp16)
__device__ int2   g_csr[NNZ_MAX];          // {col, val_bits} in CSR order
__device__ int    g_cnt[NT];               // per-row degree counts
__device__ int    g_rowptr[NT];            // block-local exclusive prefix
__device__ int    g_fill[NT];              // scatter fill cursors
__device__ int    g_bsum[SCAN_NB];         // exclusive-scanned block sums

__device__ __forceinline__ float2 h2f(unsigned u) {
    __half2 h = *reinterpret_cast<__half2*>(&u);
    return __half22float2(h);
}
__device__ __forceinline__ unsigned f2h(float a, float b) {
    __half2 h = __floats2half2_rn(a, b);
    return *reinterpret_cast<unsigned*>(&h);
}

// ---------------------------------------------------------------------------
// init: g_h0 = fp16(concat(user_emb, item_emb)); acc (=d_out) = f32 concat;
//       zero g_cnt / g_fill.
// ---------------------------------------------------------------------------
__global__ void lgcn_init(const float* __restrict__ ue,
                          const float* __restrict__ ie,
                          float* __restrict__ acc) {
    int i = blockIdx.x * blockDim.x + threadIdx.x;
    const int total4 = NT * D4;
    const int user4  = NU * D4;
    if (i < total4) {
        float4 v;
        if (i < user4) v = reinterpret_cast<const float4*>(ue)[i];
        else           v = reinterpret_cast<const float4*>(ie)[i - user4];
        reinterpret_cast<float4*>(acc)[i] = v;
        uint2 h;
        h.x = f2h(v.x, v.y);
        h.y = f2h(v.z, v.w);
        reinterpret_cast<uint2*>(g_h0)[i] = h;
    }
    if (i < NT) { g_cnt[i] = 0; g_fill[i] = 0; }
}

// ---------------------------------------------------------------------------
// histogram: count in-edges per destination row
// ---------------------------------------------------------------------------
__global__ void lgcn_hist(const int* __restrict__ row, int nnz) {
    int e = blockIdx.x * blockDim.x + threadIdx.x;
    if (e < nnz) atomicAdd(&g_cnt[row[e]], 1);
}

// ---------------------------------------------------------------------------
// scan1: per-chunk (4096 rows) exclusive prefix into g_rowptr, totals to g_bsum
// scan2: exclusive scan of the 37 chunk totals
// Final rowptr[r] = g_rowptr[r] + g_bsum[r >> SCAN_SHIFT] (resolved inline)
// ---------------------------------------------------------------------------
__global__ void lgcn_scan1() {
    __shared__ int sh[SCAN_THREADS];
    int t = threadIdx.x;
    int base = blockIdx.x * SCAN_CHUNK + t * SCAN_ITEMS;
    int v[SCAN_ITEMS];
    int s = 0;
#pragma unroll
    for (int j = 0; j < SCAN_ITEMS; j++) {
        int idx = base + j;
        v[j] = (idx < NT) ? g_cnt[idx] : 0;
        s += v[j];
    }
    sh[t] = s;
    __syncthreads();
    for (int off = 1; off < SCAN_THREADS; off <<= 1) {
        int x = sh[t];
        int y = (t >= off) ? sh[t - off] : 0;
        __syncthreads();
        sh[t] = x + y;
        __syncthreads();
    }
    int excl = sh[t] - s;
#pragma unroll
    for (int j = 0; j < SCAN_ITEMS; j++) {
        int idx = base + j;
        if (idx < NT) g_rowptr[idx] = excl;
        excl += v[j];
    }
    if (t == SCAN_THREADS - 1) g_bsum[blockIdx.x] = sh[SCAN_THREADS - 1];
}

__global__ void lgcn_scan2() {
    __shared__ int sh[64];
    int t = threadIdx.x;
    int v = (t < SCAN_NB) ? g_bsum[t] : 0;
    sh[t] = v;
    __syncthreads();
    for (int off = 1; off < 64; off <<= 1) {
        int x = sh[t];
        int y = (t >= off) ? sh[t - off] : 0;
        __syncthreads();
        sh[t] = x + y;
        __syncthreads();
    }
    if (t < SCAN_NB) g_bsum[t] = sh[t] - v;   // exclusive
}

// ---------------------------------------------------------------------------
// scatter edges into CSR order (rowptr resolved inline with bsum)
// ---------------------------------------------------------------------------
__global__ void lgcn_scatter(const int* __restrict__ row,
                             const int* __restrict__ col,
                             const float* __restrict__ val,
                             int nnz) {
    int e = blockIdx.x * blockDim.x + threadIdx.x;
    if (e >= nnz) return;
    int r = row[e];
    int base = g_rowptr[r] + g_bsum[r >> SCAN_SHIFT];
    int pos  = base + atomicAdd(&g_fill[r], 1);
    g_csr[pos] = make_int2(col[e], __float_as_int(val[e]));
}

// ---------------------------------------------------------------------------
// CSR SpMM: fp16 gather (128B/row = 1 L2 line), f32 register accumulate.
// 16 lanes per row; each lane owns 4 dims (8B of the fp16 row).
//   layer 0: h1[r] = sum val*h0[col]
//   layer 1: h2[r] = sum val*h1[col]
//   layer 2: no next store; acc[r] = 0.25*(acc[r] + h1[r] + h2[r] + sum)
// Edge pairs loaded 16-wide with next-chunk prefetch; shfl uses the 16-lane
// GROUP member mask (tails differ between the two groups of a warp).
// Buffers resolved from __device__ symbols IN DEVICE CODE (host-side symbol
// addresses are host shadows; ATS makes that silently wrong on GB300).
// ---------------------------------------------------------------------------
__global__ void lgcn_spmm_csr(float* __restrict__ acc, int layer, int nnz) {
    const __half* __restrict__ cur  = (layer == 0) ? g_h0 :
                                      (layer == 1) ? g_h1 : g_h2;
    __half*       __restrict__ next = (layer == 0) ? g_h1 : g_h2;

    int t   = blockIdx.x * blockDim.x + threadIdx.x;
    int r   = t >> 4;          // row
    int seg = t & 15;          // 8B segment within the 128B fp16 row
    if (r >= NT) return;
    unsigned gmask = 0xFFFFu << (threadIdx.x & 16);

    int start = g_rowptr[r] + g_bsum[r >> SCAN_SHIFT];
    int end   = (r + 1 < NT) ? (g_rowptr[r + 1] + g_bsum[(r + 1) >> SCAN_SHIFT])
                             : nnz;

    float s0 = 0.f, s1 = 0.f, s2 = 0.f, s3 = 0.f;
    const uint2* cur2 = reinterpret_cast<const uint2*>(cur);

    int k = start;
    int2 cv = make_int2(0, 0);
    if (k + seg < end) cv = __ldg(&g_csr[k + seg]);

    for (; k + 16 <= end; ) {            // full 16-edge chunks, prefetched
        int2 use = cv;
        int kn = k + 16;
        if (kn + seg < end) cv = __ldg(&g_csr[kn + seg]);
#pragma unroll
        for (int j = 0; j < 16; j++) {
            int   c = __shfl_sync(gmask, use.x, j, 16);
            float v = __int_as_float(__shfl_sync(gmask, use.y, j, 16));
            uint2 h = __ldg(cur2 + (size_t)c * 16 + seg);
            float2 f0 = h2f(h.x), f1 = h2f(h.y);
            s0 += v * f0.x; s1 += v * f0.y; s2 += v * f1.x; s3 += v * f1.y;
        }
        k = kn;
    }
    int rem = end - k;                    // tail 0..15, uniform within group
    for (int j = 0; j < rem; j++) {
        int   c = __shfl_sync(gmask, cv.x, j, 16);
        float v = __int_as_float(__shfl_sync(gmask, cv.y, j, 16));
        uint2 h = __ldg(cur2 + (size_t)c * 16 + seg);
        float2 f0 = h2f(h.x), f1 = h2f(h.y);
        s0 += v * f0.x; s1 += v * f0.y; s2 += v * f1.x; s3 += v * f1.y;
    }

    size_t o = (size_t)r * 16 + seg;      // uint2 index == float4 index
    if (layer < 2) {
        uint2 h;
        h.x = f2h(s0, s1);
        h.y = f2h(s2, s3);
        reinterpret_cast<uint2*>(next)[o] = h;
    } else {
        // acc = 0.25 * (e0(acc) + e1(h1) + e2(h2) + s)
        uint2 e1 = reinterpret_cast<const uint2*>(g_h1)[o];
        uint2 e2 = reinterpret_cast<const uint2*>(g_h2)[o];
        float2 a1 = h2f(e1.x), b1 = h2f(e1.y);
        float2 a2 = h2f(e2.x), b2 = h2f(e2.y);
        float4 a = reinterpret_cast<float4*>(acc)[o];
        a.x = 0.25f * (a.x + a1.x + a2.x + s0);
        a.y = 0.25f * (a.y + a1.y + a2.y + s1);
        a.z = 0.25f * (a.z + b1.x + b2.x + s2);
        a.w = 0.25f * (a.w + b1.y + b2.y + s3);
        reinterpret_cast<float4*>(acc)[o] = a;
    }
}

// ---------------------------------------------------------------------------
// launch
// Inputs (metadata order): user_emb f32 [NU*D], item_emb f32 [NI*D],
//                          adj_row i32 [NNZ], adj_col i32 [NNZ], adj_val f32 [NNZ]
// Output: mean_emb f32 [NT*D] (users then items)
// ---------------------------------------------------------------------------
extern "C" void kernel_launch(void* const* d_in, const int* in_sizes, int n_in,
                              void* d_out, int out_size) {
    const float* ue   = (const float*)d_in[0];
    const float* ie   = (const float*)d_in[1];
    const int*   arow = (const int*)d_in[2];
    const int*   acol = (const int*)d_in[3];
    const float* aval = (const float*)d_in[4];
    float* acc = (float*)d_out;

    int nnz = in_sizes[2];
    if (nnz > NNZ_MAX) nnz = NNZ_MAX;   // static scratch bound (dataset-fixed)

    const int THREADS = 256;
    const int total4   = NT * D4;                           // 2.4M
    const int gridInit = (total4 + THREADS - 1) / THREADS;  // also covers NT
    const int gridEdge = (nnz + THREADS - 1) / THREADS;
    const int gridSpmm = (NT * 16 + THREADS - 1) / THREADS;

    lgcn_init<<<gridInit, THREADS>>>(ue, ie, acc);
    lgcn_hist<<<gridEdge, THREADS>>>(arow, nnz);
    lgcn_scan1<<<SCAN_NB, SCAN_THREADS>>>();
    lgcn_scan2<<<1, 64>>>();
    lgcn_scatter<<<gridEdge, THREADS>>>(arow, acol, aval, nnz);

    for (int l = 0; l < NLAYERS; l++)
        lgcn_spmm_csr<<<gridSpmm, THREADS>>>(acc, l, nnz);
}